// round 10
// baseline (speedup 1.0000x reference)
#include <cuda_runtime.h>
#include <math.h>

#define T_SAMPLES 128
#define HID 16
#define HPAIRS (HID / 2)
#define RPT 2   // rays per thread

typedef unsigned long long u64;

#define LOG2E 1.4426950408889634f

// ---- packed f32x2 helpers (sm_100+; emits FFMA2 in SASS) ----
__device__ __forceinline__ u64 pack2(float lo, float hi) {
    u64 r; asm("mov.b64 %0, {%1,%2};" : "=l"(r) : "f"(lo), "f"(hi)); return r;
}
__device__ __forceinline__ void unpack2(u64 v, float& lo, float& hi) {
    asm("mov.b64 {%0,%1}, %2;" : "=f"(lo), "=f"(hi) : "l"(v));
}
__device__ __forceinline__ u64 fma2(u64 a, u64 b, u64 c) {
    u64 r; asm("fma.rn.f32x2 %0, %1, %2, %3;" : "=l"(r) : "l"(a), "l"(b), "l"(c));
    return r;
}
__device__ __forceinline__ u64 relu2(u64 v) {
    float lo, hi;
    unpack2(v, lo, hi);
    lo = fmaxf(lo, 0.0f);     // FMNMX -> alu pipe
    hi = fmaxf(hi, 0.0f);
    return pack2(lo, hi);
}
__device__ __forceinline__ float ex2(float x) {
    float r; asm("ex2.approx.f32 %0, %1;" : "=f"(r) : "f"(x)); return r;
}
__device__ __forceinline__ float lg2(float x) {
    float r; asm("lg2.approx.f32 %0, %1;" : "=f"(r) : "f"(x)); return r;
}
__device__ __forceinline__ float rcp(float x) {
    float r; asm("rcp.approx.f32 %0, %1;" : "=f"(r) : "f"(x)); return r;
}

__global__ void __launch_bounds__(128, 2)
nerf_render_kernel(const float* __restrict__ o,
                   const float* __restrict__ d,
                   const float* __restrict__ tnear,
                   const float* __restrict__ tfar,
                   const float* __restrict__ noise,
                   const float* __restrict__ W1,      // (3,16)
                   const float* __restrict__ b1,      // (16)
                   const float* __restrict__ w_sigma, // (16,1)
                   const float* __restrict__ W_rgb,   // (16,3)
                   float* __restrict__ out,           // (N,5)
                   int N)
{
    const int tid = threadIdx.x;
    const int base = blockIdx.x * (128 * RPT);

    int ridx[RPT];
    bool valid[RPT];
#pragma unroll
    for (int r = 0; r < RPT; r++) {
        const int ray = base + r * 128 + tid;
        valid[r] = (ray < N);
        ridx[r] = valid[r] ? ray : (N - 1);
    }

    // ---- shared (warp-uniform) output-layer weights, packed by hidden pair ----
    u64 ws2[HPAIRS], wr0_2[HPAIRS], wr1_2[HPAIRS], wr2_2[HPAIRS];
#pragma unroll
    for (int p = 0; p < HPAIRS; p++) {
        const int j = 2 * p;
        ws2[p]   = pack2(__ldg(&w_sigma[j]), __ldg(&w_sigma[j + 1]));
        wr0_2[p] = pack2(__ldg(&W_rgb[j * 3 + 0]), __ldg(&W_rgb[(j + 1) * 3 + 0]));
        wr1_2[p] = pack2(__ldg(&W_rgb[j * 3 + 1]), __ldg(&W_rgb[(j + 1) * 3 + 1]));
        wr2_2[p] = pack2(__ldg(&W_rgb[j * 3 + 2]), __ldg(&W_rgb[(j + 1) * 3 + 2]));
    }

    // ---- per-ray geometry + layer-1 fold: pre_j(t) = A_j + t * B_j ----
    u64 Ap[RPT][HPAIRS], Bp[RPT][HPAIRS];
    float dn[RPT], tn[RPT], tf[RPT], step[RPT], ts_prev[RPT];
    float Ttr[RPT], c0[RPT], c1[RPT], c2[RPT], dep[RPT], alp[RPT];

#pragma unroll
    for (int r = 0; r < RPT; r++) {
        const int ray = ridx[r];
        const float ox = o[3 * ray + 0], oy = o[3 * ray + 1], oz = o[3 * ray + 2];
        const float dx = d[3 * ray + 0], dy = d[3 * ray + 1], dz = d[3 * ray + 2];
        dn[r] = sqrtf(dx * dx + dy * dy + dz * dz);
        tn[r] = tnear[ray];
        tf[r] = tfar[ray];
        step[r] = (tf[r] - tn[r]) * (1.0f / (float)T_SAMPLES);

#pragma unroll
        for (int p = 0; p < HPAIRS; p++) {
            const int j = 2 * p;
            const float w1x0 = __ldg(&W1[0 * HID + j]), w1x1 = __ldg(&W1[0 * HID + j + 1]);
            const float w1y0 = __ldg(&W1[1 * HID + j]), w1y1 = __ldg(&W1[1 * HID + j + 1]);
            const float w1z0 = __ldg(&W1[2 * HID + j]), w1z1 = __ldg(&W1[2 * HID + j + 1]);
            const float A0 = fmaf(ox, w1x0, fmaf(oy, w1y0, fmaf(oz, w1z0, __ldg(&b1[j]))));
            const float A1 = fmaf(ox, w1x1, fmaf(oy, w1y1, fmaf(oz, w1z1, __ldg(&b1[j + 1]))));
            const float B0 = fmaf(dx, w1x0, fmaf(dy, w1y0, dz * w1z0));
            const float B1 = fmaf(dx, w1x1, fmaf(dy, w1y1, dz * w1z1));
            Ap[r][p] = pack2(A0, A1);
            Bp[r][p] = pack2(B0, B1);
        }

        ts_prev[r] = fmaf(step[r], noise[ray], tn[r]);
        Ttr[r] = 1.0f;
        c0[r] = c1[r] = c2[r] = dep[r] = alp[r] = 0.0f;
    }

#pragma unroll 2
    for (int t = 1; t <= T_SAMPLES; t++) {
        // --- both rays' sample positions (independent loads) ---
        float ts[RPT], nk[RPT];
#pragma unroll
        for (int r = 0; r < RPT; r++) {
            float tsv;
            if (t < T_SAMPLES) {
                const float u = __ldg(&noise[(size_t)t * N + ridx[r]]);
                tsv = fmaf(step[r], (float)t + u, tn[r]);
            } else {
                tsv = tf[r];
            }
            ts[r] = tsv;
            nk[r] = (ts_prev[r] - tsv) * dn[r];   // -delta * dn
        }

        // --- interleaved MLPs (shared weight regs) ---
        u64 sacc[RPT], racc0[RPT], racc1[RPT], racc2[RPT];
        u64 tp[RPT];
#pragma unroll
        for (int r = 0; r < RPT; r++) {
            tp[r] = pack2(ts_prev[r], ts_prev[r]);
            sacc[r] = racc0[r] = racc1[r] = racc2[r] = 0ull;
        }
#pragma unroll
        for (int p = 0; p < HPAIRS; p++) {
#pragma unroll
            for (int r = 0; r < RPT; r++) {
                u64 hp = fma2(tp[r], Bp[r][p], Ap[r][p]);
                hp = relu2(hp);
                sacc[r]  = fma2(hp, ws2[p],   sacc[r]);
                racc0[r] = fma2(hp, wr0_2[p], racc0[r]);
                racc1[r] = fma2(hp, wr1_2[p], racc1[r]);
                racc2[r] = fma2(hp, wr2_2[p], racc2[r]);
            }
        }

        // --- independent epilogues ---
#pragma unroll
        for (int r = 0; r < RPT; r++) {
            float xl, xh;
            unpack2(sacc[r], xl, xh);  const float acc_s = xl + xh;
            unpack2(racc0[r], xl, xh); const float r0 = xl + xh;
            unpack2(racc1[r], xl, xh); const float r1 = xl + xh;
            unpack2(racc2[r], xl, xh); const float r2 = xl + xh;

            // fused softplus+exp:  e = 2^( -k * log2(1 + 2^(a*log2e)) )
            const float l = lg2(1.0f + ex2(acc_s * LOG2E));
            const float e = ex2(nk[r] * l);
            const float w = Ttr[r] * (1.0f - e);
            Ttr[r] *= e;

            const float s0 = rcp(1.0f + ex2(-r0 * LOG2E));
            const float s1 = rcp(1.0f + ex2(-r1 * LOG2E));
            const float s2 = rcp(1.0f + ex2(-r2 * LOG2E));

            c0[r]  = fmaf(w, s0, c0[r]);
            c1[r]  = fmaf(w, s1, c1[r]);
            c2[r]  = fmaf(w, s2, c2[r]);
            dep[r] = fmaf(w, ts_prev[r], dep[r]);
            alp[r] += w;

            ts_prev[r] = ts[r];
        }
    }

#pragma unroll
    for (int r = 0; r < RPT; r++) {
        if (valid[r]) {
            const int ray = ridx[r];
            out[5 * ray + 0] = c0[r];
            out[5 * ray + 1] = c1[r];
            out[5 * ray + 2] = c2[r];
            out[5 * ray + 3] = dep[r];
            out[5 * ray + 4] = alp[r];
        }
    }
}

extern "C" void kernel_launch(void* const* d_in, const int* in_sizes, int n_in,
                              void* d_out, int out_size)
{
    const float* o       = (const float*)d_in[0];
    const float* d       = (const float*)d_in[1];
    const float* tnear   = (const float*)d_in[2];
    const float* tfar    = (const float*)d_in[3];
    const float* noise   = (const float*)d_in[4];
    const float* W1      = (const float*)d_in[5];
    const float* b1      = (const float*)d_in[6];
    const float* w_sigma = (const float*)d_in[7];
    const float* W_rgb   = (const float*)d_in[8];
    float* out = (float*)d_out;

    const int N = in_sizes[2];  // tnear element count
    const int threads = 128;
    const int rays_per_block = threads * RPT;
    const int blocks = (N + rays_per_block - 1) / rays_per_block;
    nerf_render_kernel<<<blocks, threads>>>(o, d, tnear, tfar, noise,
                                            W1, b1, w_sigma, W_rgb, out, N);
}